// round 7
// baseline (speedup 1.0000x reference)
#include <cuda_runtime.h>
#include <math.h>
#include <stdint.h>

// ---------------- problem constants ----------------
#define SCALE 0.17677669529663687f
#define NBUF (2*384*1024)     // 786432
#define NGRP 12

// ---------------- scratch ----------------
__device__ float g_q [NBUF];
__device__ float g_xs[NBUF];
__device__ float g_k [NBUF];
__device__ float g_v [NBUF];
__device__ float g_o [NBUF];
__device__ float2 g_pos[NGRP*1024];

__device__ __forceinline__ uint32_t f2tf(float f) {
    uint32_t u; asm("cvt.rna.tf32.f32 %0, %1;" : "=r"(u) : "f"(f)); return u;
}
__device__ __forceinline__ void mma_tf32(float* d, const uint32_t* a, const uint32_t* b) {
    asm volatile("mma.sync.aligned.m16n8k8.row.col.f32.tf32.tf32.f32 "
        "{%0,%1,%2,%3}, {%4,%5,%6,%7}, {%8,%9}, {%0,%1,%2,%3};"
        : "+f"(d[0]), "+f"(d[1]), "+f"(d[2]), "+f"(d[3])
        : "r"(a[0]), "r"(a[1]), "r"(a[2]), "r"(a[3]), "r"(b[0]), "r"(b[1]));
}

// =======================================================================
// transpose x [b][c][n] -> xT [b][n][c]
// =======================================================================
__global__ __launch_bounds__(256) void transpose_kernel(
    const float* __restrict__ x, float* __restrict__ xT)
{
    __shared__ float t[32][33];
    int n0 = blockIdx.x * 32, c0 = blockIdx.y * 32, b = blockIdx.z;
    int tx = threadIdx.x & 31, ty = threadIdx.x >> 5;
    #pragma unroll
    for (int i = 0; i < 4; i++)
        t[ty + i*8][tx] = x[((size_t)(b*384 + c0 + ty + i*8))*1024 + n0 + tx];
    __syncthreads();
    #pragma unroll
    for (int i = 0; i < 4; i++)
        xT[((size_t)(b*1024 + n0 + ty + i*8))*384 + c0 + tx] = t[tx][ty + i*8];
}

// =======================================================================
// tf32 mma.sync GEMM: D[n0+128][o0+64] = sum_c A[n][c] W[o][c] + bias[o]
// A pixel-major [1024][384], W [384][384] row-major (K-major both).
// 8 warps = 4(m) x 2(n); warp tile 32x32; K chunks of 32, double-buffered.
// =======================================================================
#define ASTRIDE 36
__device__ void gemm_mma_body(
    const float* __restrict__ A, const float* __restrict__ W,
    const float* __restrict__ bias, float* __restrict__ Y,
    int n0, int o0, int transOut)
{
    extern __shared__ float dsm[];
    float* As = dsm;                 // [2][128*36]
    float* Bs = dsm + 2*128*ASTRIDE; // [2][64*36]

    int tid = threadIdx.x, lane = tid & 31, wid = tid >> 5;
    int wm = wid & 3, wn = wid >> 2;

    int ar = tid >> 1, ah = (tid & 1) * 16;
    int br = tid >> 2, bq = (tid & 3) * 8;
    const float* Ap = A + (size_t)(n0 + ar) * 384 + ah;
    const float* Wp = W + (size_t)(o0 + br) * 384 + bq;

    float4 pa[4]; float4 pb[2];
    #pragma unroll
    for (int i = 0; i < 4; i++) pa[i] = *(const float4*)(Ap + i*4);
    #pragma unroll
    for (int i = 0; i < 2; i++) pb[i] = *(const float4*)(Wp + i*4);

    float acc[2][4][4];
    #pragma unroll
    for (int mt = 0; mt < 2; mt++)
        #pragma unroll
        for (int nt = 0; nt < 4; nt++)
            #pragma unroll
            for (int i = 0; i < 4; i++) acc[mt][nt][i] = 0.f;

    int buf = 0;
    int g = lane >> 2, c = lane & 3;

    #pragma unroll 1
    for (int ch = 0; ch < 12; ch++) {
        float* Asb = As + buf * 128 * ASTRIDE;
        float* Bsb = Bs + buf * 64 * ASTRIDE;
        #pragma unroll
        for (int i = 0; i < 4; i++) {
            uint4 t = make_uint4(f2tf(pa[i].x), f2tf(pa[i].y), f2tf(pa[i].z), f2tf(pa[i].w));
            *(uint4*)&Asb[ar*ASTRIDE + ah + i*4] = t;
        }
        #pragma unroll
        for (int i = 0; i < 2; i++) {
            uint4 t = make_uint4(f2tf(pb[i].x), f2tf(pb[i].y), f2tf(pb[i].z), f2tf(pb[i].w));
            *(uint4*)&Bsb[br*ASTRIDE + bq + i*4] = t;
        }
        __syncthreads();
        if (ch < 11) {
            #pragma unroll
            for (int i = 0; i < 4; i++) pa[i] = *(const float4*)(Ap + (ch+1)*32 + i*4);
            #pragma unroll
            for (int i = 0; i < 2; i++) pb[i] = *(const float4*)(Wp + (ch+1)*32 + i*4);
        }
        const uint32_t* Au = (const uint32_t*)Asb;
        const uint32_t* Bu = (const uint32_t*)Bsb;
        #pragma unroll
        for (int kk = 0; kk < 4; kk++) {
            uint32_t afr[2][4];
            #pragma unroll
            for (int mt = 0; mt < 2; mt++) {
                int rb = wm*32 + mt*16;
                afr[mt][0] = Au[(rb + g    )*ASTRIDE + kk*8 + c];
                afr[mt][1] = Au[(rb + g + 8)*ASTRIDE + kk*8 + c];
                afr[mt][2] = Au[(rb + g    )*ASTRIDE + kk*8 + c + 4];
                afr[mt][3] = Au[(rb + g + 8)*ASTRIDE + kk*8 + c + 4];
            }
            #pragma unroll
            for (int nt = 0; nt < 4; nt++) {
                int nb = wn*32 + nt*8;
                uint32_t bfr[2];
                bfr[0] = Bu[(nb + g)*ASTRIDE + kk*8 + c];
                bfr[1] = Bu[(nb + g)*ASTRIDE + kk*8 + c + 4];
                mma_tf32(acc[0][nt], afr[0], bfr);
                mma_tf32(acc[1][nt], afr[1], bfr);
            }
        }
        buf ^= 1;
    }

    int c2 = (lane & 3) * 2;
    #pragma unroll
    for (int mt = 0; mt < 2; mt++) {
        int r0 = wm*32 + mt*16 + g;
        #pragma unroll
        for (int nt = 0; nt < 4; nt++) {
            int col = o0 + wn*32 + nt*8 + c2;
            float b0 = bias[col], b1 = bias[col + 1];
            if (!transOut) {
                float2 v0 = make_float2(acc[mt][nt][0] + b0, acc[mt][nt][1] + b1);
                float2 v1 = make_float2(acc[mt][nt][2] + b0, acc[mt][nt][3] + b1);
                *(float2*)&Y[(size_t)(n0 + r0    )*384 + col] = v0;
                *(float2*)&Y[(size_t)(n0 + r0 + 8)*384 + col] = v1;
            } else {
                Y[(size_t)(col    )*1024 + n0 + r0    ] = acc[mt][nt][0] + b0;
                Y[(size_t)(col + 1)*1024 + n0 + r0    ] = acc[mt][nt][1] + b1;
                Y[(size_t)(col    )*1024 + n0 + r0 + 8] = acc[mt][nt][2] + b0;
                Y[(size_t)(col + 1)*1024 + n0 + r0 + 8] = acc[mt][nt][3] + b1;
            }
        }
    }
}

__global__ __launch_bounds__(256) void gemm_mma(
    const float* __restrict__ A, const float* __restrict__ W,
    const float* __restrict__ bias, float* __restrict__ Y, int transOut)
{
    int b = blockIdx.z;
    gemm_mma_body(A + (size_t)b*393216, W, bias, Y + (size_t)b*393216,
                  blockIdx.x*128, blockIdx.y*64, transOut);
}

__global__ __launch_bounds__(256) void gemm_mma_kv(
    const float* __restrict__ A,
    const float* __restrict__ Wk, const float* __restrict__ bk,
    const float* __restrict__ Wv, const float* __restrict__ bv,
    float* __restrict__ Yk, float* __restrict__ Yv)
{
    int b = blockIdx.z;
    int sel = blockIdx.y >= 6;
    int o0 = (blockIdx.y - sel*6) * 64;
    gemm_mma_body(A + (size_t)b*393216, sel ? Wv : Wk, sel ? bv : bk,
                  (sel ? Yv : Yk) + (size_t)b*393216, blockIdx.x*128, o0, 0);
}

// =======================================================================
// depthwise 7x7 conv, pixel-major. block = (bg, band of 4 rows)
// =======================================================================
__global__ __launch_bounds__(256) void dwconv_kernel(
    const float* __restrict__ q, const float* __restrict__ dw_w,
    const float* __restrict__ dw_b, float* __restrict__ tmp)
{
    extern __shared__ float s[];          // [10 rows][32 px][64 ch]
    int bg = blockIdx.x >> 3;
    int r0 = (blockIdx.x & 7) * 4;
    int b = bg / 6, g = bg % 6;
    int tid = threadIdx.x;
    const float* qb = q + ((size_t)b*1024)*384 + g*64;

    #pragma unroll
    for (int l = 0; l < 20; l++) {
        int f = (tid + l*256) * 4;
        int row = f >> 11;
        int rem = f & 2047;
        int px = rem >> 6, ch4 = rem & 63;
        int iy = r0 - 3 + row;
        float4 val = make_float4(0.f, 0.f, 0.f, 0.f);
        if (iy >= 0 && iy < 32)
            val = *(const float4*)(qb + ((size_t)(iy*32 + px))*384 + ch4);
        *(float4*)&s[f] = val;
    }
    int ch = tid & 63, pq = tid >> 6;
    float wreg[49];
    #pragma unroll
    for (int i = 0; i < 49; i++) wreg[i] = dw_w[ch*49 + i];
    float bch = dw_b[ch];
    __syncthreads();

    #pragma unroll
    for (int orow = 0; orow < 4; orow++) {
        #pragma unroll
        for (int pxi = 0; pxi < 8; pxi++) {
            int px = pq*8 + pxi;
            float a = bch;
            #pragma unroll
            for (int ky = 0; ky < 7; ky++) {
                int srow = orow + ky;
                #pragma unroll
                for (int kx = 0; kx < 7; kx++) {
                    int ix = px + kx - 3;
                    if (ix >= 0 && ix < 32)
                        a += wreg[ky*7+kx] * s[(srow*32 + ix)*64 + ch];
                }
            }
            tmp[((size_t)bg*1024 + (r0+orow)*32 + px)*64 + ch] = a;
        }
    }
}

// =======================================================================
// LN(ch) + GELU + 1x1(2ch) + tanh -> pos. input pixel-major [bg][pix][64]
// =======================================================================
__global__ __launch_bounds__(256) void offs_kernel(
    const float* __restrict__ tmp, const float* __restrict__ ln_g,
    const float* __restrict__ ln_b, const float* __restrict__ pw_w,
    float2* __restrict__ pos)
{
    int bg = blockIdx.x >> 3;
    int p0 = (blockIdx.x & 7) * 128;
    int tid = threadIdx.x;
    int pl = tid & 127, half = tid >> 7;
    int pix = p0 + pl;
    const float* tp = tmp + ((size_t)bg*1024 + pix)*64 + half*32;

    __shared__ float red[256], red2[256], mu_s[128], rs_s[128];

    float vals[32];
    float s1 = 0.f;
    #pragma unroll
    for (int i4 = 0; i4 < 8; i4++) {
        float4 v4 = *(const float4*)(tp + i4*4);
        vals[i4*4+0] = v4.x; vals[i4*4+1] = v4.y;
        vals[i4*4+2] = v4.z; vals[i4*4+3] = v4.w;
        s1 += v4.x + v4.y + v4.z + v4.w;
    }
    red[tid] = s1;
    __syncthreads();
    if (half == 0) mu_s[pl] = (red[pl] + red[pl+128]) * (1.f/64.f);
    __syncthreads();
    float mu = mu_s[pl];
    float s2 = 0.f;
    #pragma unroll
    for (int i = 0; i < 32; i++) { float d = vals[i]-mu; s2 += d*d; }
    red[tid] = s2;
    __syncthreads();
    if (half == 0) rs_s[pl] = rsqrtf((red[pl]+red[pl+128])*(1.f/64.f) + 1e-5f);
    __syncthreads();
    float rs = rs_s[pl];
    float sy = 0.f, sx = 0.f;
    #pragma unroll
    for (int i = 0; i < 32; i++) {
        int c = half*32 + i;
        float o = (vals[i]-mu)*rs*ln_g[c] + ln_b[c];
        o = 0.5f*o*(1.f + erff(o*0.70710678118654752f));
        sy += o * pw_w[c];
        sx += o * pw_w[64+c];
    }
    red[tid] = sy; red2[tid] = sx;
    __syncthreads();
    if (half == 0) {
        float oy = tanhf(red[pl]+red[pl+128]) * 0.0625f;
        float ox = tanhf(red2[pl]+red2[pl+128]) * 0.0625f;
        int py = pix >> 5, px = pix & 31;
        float refy = ((py + 0.5f)*(1.f/16.f)) - 1.f;
        float refx = ((px + 0.5f)*(1.f/16.f)) - 1.f;
        pos[bg*1024 + pix] = make_float2(ox + refx, oy + refy);
    }
}

// =======================================================================
// grid sample x (channel-major input) at pos -> xs pixel-major [b][s][384]
// =======================================================================
__global__ __launch_bounds__(256) void sample_kernel(
    const float* __restrict__ x, const float2* __restrict__ pos,
    float* __restrict__ xs)
{
    int idx = blockIdx.x * 256 + threadIdx.x;
    int gc = idx & 63;
    int s  = (idx >> 6) & 1023;
    int bg = idx >> 16;
    int b = bg / 6, g = bg % 6;
    float2 p = pos[bg * 1024 + s];
    float gx = (p.x + 1.f) * 0.5f * 31.f;
    float gy = (p.y + 1.f) * 0.5f * 31.f;
    float x0f = floorf(gx), y0f = floorf(gy);
    float wx = gx - x0f, wy = gy - y0f;
    int x0 = (int)x0f, y0 = (int)y0f;
    const float* xp = x + ((size_t)(b*384 + g*64 + gc))*1024;
    float r = 0.f;
    bool vx0 = (x0 >= 0) & (x0 <= 31), vx1 = (x0 >= -1) & (x0 <= 30);
    bool vy0 = (y0 >= 0) & (y0 <= 31), vy1 = (y0 >= -1) & (y0 <= 30);
    if (vx0 && vy0) r += (1.f - wx) * (1.f - wy) * xp[y0 * 32 + x0];
    if (vx1 && vy0) r += wx * (1.f - wy) * xp[y0 * 32 + x0 + 1];
    if (vx0 && vy1) r += (1.f - wx) * wy * xp[(y0 + 1) * 32 + x0];
    if (vx1 && vy1) r += wx * wy * xp[(y0 + 1) * 32 + x0 + 1];
    xs[((size_t)(b*1024) + s)*384 + g*64 + gc] = r;
}

// =======================================================================
// fused attention, pixel-major q/k/v, M=16 rows per block.
// smem floats: p[1024*20] | kv[256*36] | q[512] | redw[128] | fin[32]
// =======================================================================
#define P_STRIDE 20
#define KV_STRIDE 36
__global__ __launch_bounds__(256) void attn_kernel(
    const float* __restrict__ qg, const float* __restrict__ kg,
    const float* __restrict__ vg, const float2* __restrict__ pos,
    const float* __restrict__ rpe, float* __restrict__ out)
{
    extern __shared__ float sm[];
    float* p_s  = sm;                       // 20480
    float* kv_s = sm + 20480;               // 9216
    float* q_s  = sm + 20480 + 9216;        // 512  [r*32 + c]
    float* redw = q_s + 512;                // 128
    float* fin  = redw + 128;               // 32

    int bh = blockIdx.y;
    int m0 = blockIdx.x * 16;
    int b = bh / 12, head = bh % 12;
    int bg = b * 6 + (head >> 1);
    int hc = head * 32;
    int tid = threadIdx.x;
    int lane = tid & 31, warp = tid >> 5;

    const float* qb = qg + ((size_t)b*1024)*384 + hc;
    const float* kb = kg + ((size_t)b*1024)*384 + hc;
    const float* vb = vg + ((size_t)b*1024)*384 + hc;

    #pragma unroll
    for (int i = tid; i < 512; i += 256) {
        int r = i >> 5, c = i & 31;
        q_s[r*32 + c] = qb[(size_t)(m0 + r)*384 + c] * SCALE;
    }
    __syncthreads();

    float acc[16][4] = {};

    // ---- scores with register-prefetched k chunks
    float4 kp[8];
    {
        const float* p0 = kb + (size_t)tid * 384;
        #pragma unroll
        for (int i = 0; i < 8; i++) kp[i] = *(const float4*)(p0 + i*4);
    }
    #pragma unroll 1
    for (int j = 0; j < 4; j++) {
        #pragma unroll
        for (int i = 0; i < 8; i++) *(float4*)&kv_s[tid*KV_STRIDE + i*4] = kp[i];
        __syncthreads();
        if (j < 3) {
            const float* pn = kb + (size_t)((j+1)*256 + tid) * 384;
            #pragma unroll
            for (int i = 0; i < 8; i++) kp[i] = *(const float4*)(pn + i*4);
        }
        #pragma unroll
        for (int cg = 0; cg < 8; cg++) {
            float4 kq = *(const float4*)&kv_s[tid*KV_STRIDE + cg*4];
            #pragma unroll
            for (int r = 0; r < 16; r++) {
                float4 q4 = *(const float4*)&q_s[r*32 + cg*4];
                acc[r][j] = fmaf(q4.x, kq.x, acc[r][j]);
                acc[r][j] = fmaf(q4.y, kq.y, acc[r][j]);
                acc[r][j] = fmaf(q4.z, kq.z, acc[r][j]);
                acc[r][j] = fmaf(q4.w, kq.w, acc[r][j]);
            }
        }
        __syncthreads();
    }

    // ---- RPE bilinear bias (y constant over the 16 rows of this block)
    {
        const float* T = rpe + head * 3969;
        int yq = m0 >> 5, xb = m0 & 31;
        float qy  = (yq + 0.5f) * (1.f/16.f) - 1.f;
        float qx0 = (xb + 0.5f) * (1.f/16.f) - 1.f;
        #pragma unroll
        for (int j = 0; j < 4; j++) {
            float2 p = pos[bg*1024 + tid + 256*j];
            float gy = fmaf(qy - p.y, 15.5f, 31.f);
            float y0f = floorf(gy);
            float wy = gy - y0f;
            int y0 = (int)y0f;
            float vy0 = (y0 >= 0 && y0 <= 62) ? 1.f : 0.f;
            float vy1 = (y0 >= -1 && y0 <= 61) ? 1.f : 0.f;
            int yc0 = min(max(y0, 0), 62);
            int yc1 = min(max(y0 + 1, 0), 62);
            const float* T0 = T + yc0*63;
            const float* T1 = T + yc1*63;
            float w0y = (1.f - wy) * vy0;
            float w1y = wy * vy1;
            float Cx = fmaf(qx0 - p.x, 15.5f, 31.f);
            #pragma unroll
            for (int r = 0; r < 16; r++) {
                float gx = fmaf((float)r, 0.96875f, Cx);
                float x0f = floorf(gx);
                float wx = gx - x0f;
                int x0 = (int)x0f;
                float vx0 = (x0 >= 0 && x0 <= 62) ? 1.f : 0.f;
                float vx1 = (x0 >= -1 && x0 <= 61) ? 1.f : 0.f;
                int xc0 = min(max(x0, 0), 62);
                int xc1 = min(max(x0 + 1, 0), 62);
                float t00 = T0[xc0], t01 = T0[xc1];
                float t10 = T1[xc0], t11 = T1[xc1];
                float wx0 = (1.f - wx) * vx0, wx1 = wx * vx1;
                acc[r][j] += w0y * (wx0*t00 + wx1*t01) + w1y * (wx0*t10 + wx1*t11);
            }
        }
    }

    // ---- softmax
    float rv[16];
    #pragma unroll
    for (int r = 0; r < 16; r++)
        rv[r] = fmaxf(fmaxf(acc[r][0], acc[r][1]), fmaxf(acc[r][2], acc[r][3]));
    #pragma unroll
    for (int off = 16; off >= 1; off >>= 1)
        #pragma unroll
        for (int r = 0; r < 16; r++)
            rv[r] = fmaxf(rv[r], __shfl_xor_sync(0xffffffffu, rv[r], off));
    if (lane == 0)
        #pragma unroll
        for (int r = 0; r < 16; r++) redw[r*8 + warp] = rv[r];
    __syncthreads();
    if (tid < 16) {
        float m = redw[tid*8];
        #pragma unroll
        for (int w = 1; w < 8; w++) m = fmaxf(m, redw[tid*8 + w]);
        fin[tid] = m;
    }
    __syncthreads();
    #pragma unroll
    for (int r = 0; r < 16; r++) {
        float m = fin[r];
        float s = 0.f;
        #pragma unroll
        for (int j = 0; j < 4; j++) { acc[r][j] = __expf(acc[r][j] - m); s += acc[r][j]; }
        rv[r] = s;
    }
    #pragma unroll
    for (int off = 16; off >= 1; off >>= 1)
        #pragma unroll
        for (int r = 0; r < 16; r++)
            rv[r] += __shfl_xor_sync(0xffffffffu, rv[r], off);
    if (lane == 0)
        #pragma unroll
        for (int r = 0; r < 16; r++) redw[r*8 + warp] = rv[r];
    __syncthreads();
    if (tid < 16) {
        float s = 0.f;
        #pragma unroll
        for (int w = 0; w < 8; w++) s += redw[tid*8 + w];
        fin[16 + tid] = 1.f / s;
    }

    // store exp'd p transposed: p_s[n][r], stride 20
    #pragma unroll
    for (int j = 0; j < 4; j++) {
        int n = tid + 256*j;
        #pragma unroll
        for (int rq = 0; rq < 4; rq++)
            *(float4*)&p_s[n*P_STRIDE + rq*4] =
                make_float4(acc[rq*4+0][j], acc[rq*4+1][j], acc[rq*4+2][j], acc[rq*4+3][j]);
    }
    __syncthreads();

    // ---- PV
    int combo = tid >> 3;
    int split = tid & 7;
    int cq = (combo & 7) * 4;
    int rq = (combo >> 3) * 4;
    float o4[4][4] = {};
    int lr = tid >> 1, lhb = (tid & 1) * 16;

    float4 vp[4];
    {
        const float* p0 = vb + (size_t)lr * 384 + lhb;
        #pragma unroll
        for (int i = 0; i < 4; i++) vp[i] = *(const float4*)(p0 + i*4);
    }
    #pragma unroll 1
    for (int chk = 0; chk < 8; chk++) {
        #pragma unroll
        for (int i = 0; i < 4; i++) *(float4*)&kv_s[lr*KV_STRIDE + lhb + i*4] = vp[i];
        __syncthreads();
        if (chk < 7) {
            const float* pn = vb + (size_t)((chk+1)*128 + lr) * 384 + lhb;
            #pragma unroll
            for (int i = 0; i < 4; i++) vp[i] = *(const float4*)(pn + i*4);
        }
        #pragma unroll
        for (int i = 0; i < 16; i++) {
            int nl = i*8 + split;
            float4 p4 = *(const float4*)&p_s[(chk*128 + nl)*P_STRIDE + rq];
            float4 v4 = *(const float4*)&kv_s[nl*KV_STRIDE + cq];
            o4[0][0] = fmaf(p4.x, v4.x, o4[0][0]); o4[0][1] = fmaf(p4.x, v4.y, o4[0][1]);
            o4[0][2] = fmaf(p4.x, v4.z, o4[0][2]); o4[0][3] = fmaf(p4.x, v4.w, o4[0][3]);
            o4[1][0] = fmaf(p4.y, v4.x, o4[1][0]); o4[1][1] = fmaf(p4.y, v4.y, o4[1][1]);
            o4[1][2] = fmaf(p4.y, v4.z, o4[1][2]); o4[1][3] = fmaf(p4.y, v4.w, o4[1][3]);
            o4[2][0] = fmaf(p4.z, v4.x, o4[2][0]); o4[2][1] = fmaf(p4.z, v4.y, o4[2][1]);
            o4[2][2] = fmaf(p4.z, v4.z, o4[2][2]); o4[2][3] = fmaf(p4.z, v4.w, o4[2][3]);
            o4[3][0] = fmaf(p4.w, v4.x, o4[3][0]); o4[3][1] = fmaf(p4.w, v4.y, o4[3][1]);
            o4[3][2] = fmaf(p4.w, v4.z, o4[3][2]); o4[3][3] = fmaf(p4.w, v4.w, o4[3][3]);
        }
        __syncthreads();
    }
    #pragma unroll
    for (int off = 4; off >= 1; off >>= 1)
        #pragma unroll
        for (int ri = 0; ri < 4; ri++)
            #pragma unroll
            for (int ci = 0; ci < 4; ci++)
                o4[ri][ci] += __shfl_xor_sync(0xffffffffu, o4[ri][ci], off);
    if (split == 0) {
        float* ob = out + ((size_t)b*1024)*384 + hc;
        #pragma unroll
        for (int ri = 0; ri < 4; ri++) {
            float inv = fin[16 + rq + ri];
            #pragma unroll
            for (int ci = 0; ci < 4; ci++)
                ob[(size_t)(m0 + rq + ri)*384 + cq + ci] = o4[ri][ci] * inv;
        }
    }
}

// ---------------- launch ----------------
extern "C" void kernel_launch(void* const* d_in, const int* in_sizes, int n_in,
                              void* d_out, int out_size)
{
    const float* x    = (const float*)d_in[0];
    const float* Wq   = (const float*)d_in[1];
    const float* bq   = (const float*)d_in[2];
    const float* Wk   = (const float*)d_in[3];
    const float* bk   = (const float*)d_in[4];
    const float* Wv   = (const float*)d_in[5];
    const float* bv   = (const float*)d_in[6];
    const float* Wo   = (const float*)d_in[7];
    const float* bo   = (const float*)d_in[8];
    const float* dw_w = (const float*)d_in[9];
    const float* dw_b = (const float*)d_in[10];
    const float* ln_g = (const float*)d_in[11];
    const float* ln_b = (const float*)d_in[12];
    const float* pw_w = (const float*)d_in[13];
    const float* rpe  = (const float*)d_in[14];

    float *q, *xs, *k, *v, *ob;
    float2* pos;
    cudaGetSymbolAddress((void**)&q,   g_q);
    cudaGetSymbolAddress((void**)&xs,  g_xs);
    cudaGetSymbolAddress((void**)&k,   g_k);
    cudaGetSymbolAddress((void**)&v,   g_v);
    cudaGetSymbolAddress((void**)&ob,  g_o);
    cudaGetSymbolAddress((void**)&pos, g_pos);

    const int GSM = (2*128*ASTRIDE + 2*64*ASTRIDE) * 4;   // 55296 B
    cudaFuncSetAttribute(gemm_mma, cudaFuncAttributeMaxDynamicSharedMemorySize, GSM);
    cudaFuncSetAttribute(gemm_mma_kv, cudaFuncAttributeMaxDynamicSharedMemorySize, GSM);
    cudaFuncSetAttribute(dwconv_kernel, cudaFuncAttributeMaxDynamicSharedMemorySize, 81920);
    cudaFuncSetAttribute(attn_kernel, cudaFuncAttributeMaxDynamicSharedMemorySize, 121472);

    // x -> xT (in g_xs)
    transpose_kernel<<<dim3(32, 12, 2), 256>>>(x, xs);
    // Q = xT * Wq^T   (pixel-major)
    gemm_mma<<<dim3(8, 6, 2), 256, GSM>>>(xs, Wq, bq, q, 0);
    // offset branch
    dwconv_kernel<<<96, 256, 81920>>>(q, dw_w, dw_b, k);
    offs_kernel<<<96, 256>>>(k, ln_g, ln_b, pw_w, pos);
    // sample (reads original channel-major x) -> xs pixel-major
    sample_kernel<<<3072, 256>>>(x, pos, xs);
    // K, V
    gemm_mma_kv<<<dim3(8, 12, 2), 256, GSM>>>(xs, Wk, bk, Wv, bv, k, v);
    // attention
    attn_kernel<<<dim3(64, 24), 256, 121472>>>(q, k, v, pos, rpe, ob);
    // O (transposed epilogue -> channel-major output)
    gemm_mma<<<dim3(8, 6, 2), 256, GSM>>>(ob, Wo, bo, (float*)d_out, 1);
}

// round 8
// speedup vs baseline: 1.3625x; 1.3625x over previous
#include <cuda_runtime.h>
#include <math.h>
#include <stdint.h>

// ---------------- scratch ----------------
#define NBUF (2*384*1024)
__device__ float g_q [NBUF];
__device__ float g_xs[NBUF];
__device__ float g_k [NBUF];
__device__ float g_v [NBUF];
__device__ float g_o [NBUF];
__device__ float2 g_pos[12*1024];

#define SCALE 0.17677669529663687f

__device__ __forceinline__ uint32_t f2tf(float f) {
    uint32_t u; asm("cvt.rna.tf32.f32 %0, %1;" : "=r"(u) : "f"(f)); return u;
}
__device__ __forceinline__ void mma_tf32(float* d, const uint32_t* a, const uint32_t* b) {
    asm volatile("mma.sync.aligned.m16n8k8.row.col.f32.tf32.tf32.f32 "
        "{%0,%1,%2,%3}, {%4,%5,%6,%7}, {%8,%9}, {%0,%1,%2,%3};"
        : "+f"(d[0]), "+f"(d[1]), "+f"(d[2]), "+f"(d[3])
        : "r"(a[0]), "r"(a[1]), "r"(a[2]), "r"(a[3]), "r"(b[0]), "r"(b[1]));
}

// =======================================================================
// Channel-major tf32 mma GEMM: Y[b][o][n] = sum_c W[o][c] X[b][c][n] + bias[o]
// M=384(o) K=384(c) N=1024(n). Block 64x128, 8 warps = 2(m)x4(n),
// warp tile 32x32, K chunks of 32, double-buffered, 1 sync/chunk.
// A smem [64][36] (K-contig), B smem [32][136] (n-contig).
// =======================================================================
#define AS_STRIDE 36
#define BS_STRIDE 136
__device__ void gemm_body(
    const float* __restrict__ W, const float* __restrict__ bias,
    const float* __restrict__ X, float* __restrict__ Y,
    int m0, int n0)
{
    extern __shared__ float dsm[];
    float* Asm = dsm;                    // [2][64*36]  = 4608 floats
    float* Bsm = dsm + 2*64*AS_STRIDE;   // [2][32*136] = 8704 floats

    int tid = threadIdx.x, lane = tid & 31, wid = tid >> 5;
    int wm = wid & 1, wn = wid >> 1;
    int g = lane >> 2, c = lane & 3;

    int ar = tid >> 2, aq = (tid & 3) * 8;     // A loader: 64 rows x 32 k
    int kb = tid >> 3, nq = (tid & 7) * 16;    // B loader: 32 k-rows x 128 n
    const float* Wp = W + (size_t)(m0 + ar) * 384 + aq;
    const float* Xp = X + (size_t)kb * 1024 + n0 + nq;

    float4 pa[2], pb[4];
    #pragma unroll
    for (int i = 0; i < 2; i++) pa[i] = *(const float4*)(Wp + i*4);
    #pragma unroll
    for (int i = 0; i < 4; i++) pb[i] = *(const float4*)(Xp + i*4);

    float acc[2][4][4];
    #pragma unroll
    for (int mt = 0; mt < 2; mt++)
        #pragma unroll
        for (int nt = 0; nt < 4; nt++)
            #pragma unroll
            for (int i = 0; i < 4; i++) acc[mt][nt][i] = 0.f;

    int buf = 0;
    #pragma unroll 1
    for (int ch = 0; ch < 12; ch++) {
        float* Asb = Asm + buf * 64 * AS_STRIDE;
        float* Bsb = Bsm + buf * 32 * BS_STRIDE;
        #pragma unroll
        for (int i = 0; i < 2; i++) {
            uint4 t = make_uint4(f2tf(pa[i].x), f2tf(pa[i].y), f2tf(pa[i].z), f2tf(pa[i].w));
            *(uint4*)&Asb[ar*AS_STRIDE + aq + i*4] = t;
        }
        #pragma unroll
        for (int i = 0; i < 4; i++) {
            uint4 t = make_uint4(f2tf(pb[i].x), f2tf(pb[i].y), f2tf(pb[i].z), f2tf(pb[i].w));
            *(uint4*)&Bsb[kb*BS_STRIDE + nq + i*4] = t;
        }
        __syncthreads();
        if (ch < 11) {
            #pragma unroll
            for (int i = 0; i < 2; i++) pa[i] = *(const float4*)(Wp + (ch+1)*32 + i*4);
            #pragma unroll
            for (int i = 0; i < 4; i++) pb[i] = *(const float4*)(Xp + (size_t)(ch+1)*32*1024 + i*4);
        }
        const uint32_t* Au = (const uint32_t*)Asb;
        const uint32_t* Bu = (const uint32_t*)Bsb;
        #pragma unroll
        for (int kk = 0; kk < 4; kk++) {
            uint32_t afr[2][4];
            #pragma unroll
            for (int mt = 0; mt < 2; mt++) {
                int rb = wm*32 + mt*16;
                afr[mt][0] = Au[(rb + g    )*AS_STRIDE + kk*8 + c];
                afr[mt][1] = Au[(rb + g + 8)*AS_STRIDE + kk*8 + c];
                afr[mt][2] = Au[(rb + g    )*AS_STRIDE + kk*8 + c + 4];
                afr[mt][3] = Au[(rb + g + 8)*AS_STRIDE + kk*8 + c + 4];
            }
            #pragma unroll
            for (int nt = 0; nt < 4; nt++) {
                int nb = wn*32 + nt*8;
                uint32_t bfr[2];
                bfr[0] = Bu[(kk*8 + c    )*BS_STRIDE + nb + g];
                bfr[1] = Bu[(kk*8 + c + 4)*BS_STRIDE + nb + g];
                mma_tf32(acc[0][nt], afr[0], bfr);
                mma_tf32(acc[1][nt], afr[1], bfr);
            }
        }
        buf ^= 1;
    }

    int c2 = (lane & 3) * 2;
    #pragma unroll
    for (int mt = 0; mt < 2; mt++) {
        int row = m0 + wm*32 + mt*16 + g;
        float b0 = bias[row], b1 = bias[row + 8];
        #pragma unroll
        for (int nt = 0; nt < 4; nt++) {
            int col = n0 + wn*32 + nt*8 + c2;
            *(float2*)&Y[(size_t)row*1024 + col] =
                make_float2(acc[mt][nt][0] + b0, acc[mt][nt][1] + b0);
            *(float2*)&Y[(size_t)(row + 8)*1024 + col] =
                make_float2(acc[mt][nt][2] + b1, acc[mt][nt][3] + b1);
        }
    }
}

__global__ __launch_bounds__(256) void gemm_mma(
    const float* __restrict__ W, const float* __restrict__ bias,
    const float* __restrict__ X, float* __restrict__ Y)
{
    int b = blockIdx.z;
    gemm_body(W, bias, X + (size_t)b*393216, Y + (size_t)b*393216,
              blockIdx.y*64, blockIdx.x*128);
}

__global__ __launch_bounds__(256) void gemm_mma_kv(
    const float* __restrict__ Wk, const float* __restrict__ bk,
    const float* __restrict__ Wv, const float* __restrict__ bv,
    const float* __restrict__ X, float* __restrict__ Yk, float* __restrict__ Yv)
{
    int b = blockIdx.z;
    int sel = blockIdx.y >= 6;
    int m0 = (blockIdx.y - sel*6) * 64;
    gemm_body(sel ? Wv : Wk, sel ? bv : bk, X + (size_t)b*393216,
              (sel ? Yv : Yk) + (size_t)b*393216, m0, blockIdx.x*128);
}

// =======================================================================
// depthwise 7x7 conv: block = one (bg,ch) plane, smem-tiled (round-2)
// =======================================================================
__global__ __launch_bounds__(256) void dwconv_kernel(
    const float* __restrict__ q, const float* __restrict__ dw_w,
    const float* __restrict__ dw_b, float* __restrict__ tmp)
{
    int plane = blockIdx.x;            // bg*64 + ch
    int ch = plane & 63;
    __shared__ float s[1024];
    __shared__ float w[49];
    const float* qp = q + (size_t)plane * 1024;
    int tid = threadIdx.x;
    *(float4*)&s[tid*4] = *(const float4*)(qp + tid*4);
    if (tid < 49) w[tid] = dw_w[ch*49 + tid];
    float bch = dw_b[ch];
    __syncthreads();
    #pragma unroll
    for (int pp = 0; pp < 4; pp++) {
        int pix = tid + pp*256;
        int py = pix >> 5, px = pix & 31;
        float a = bch;
        #pragma unroll
        for (int ky = 0; ky < 7; ky++) {
            int iy = py + ky - 3;
            if (iy < 0 || iy > 31) continue;
            #pragma unroll
            for (int kx = 0; kx < 7; kx++) {
                int ix = px + kx - 3;
                if (ix < 0 || ix > 31) continue;
                a += w[ky*7+kx] * s[iy*32+ix];
            }
        }
        tmp[(size_t)plane*1024 + pix] = a;
    }
}

// =======================================================================
// LN(ch) + GELU + 1x1(2ch) + tanh -> pos (round-2, channel-major input)
// =======================================================================
__global__ __launch_bounds__(256) void offs_kernel(
    const float* __restrict__ tmp, const float* __restrict__ ln_g,
    const float* __restrict__ ln_b, const float* __restrict__ pw_w,
    float2* __restrict__ pos)
{
    int bg = blockIdx.x >> 3;
    int p0 = (blockIdx.x & 7) * 128;
    int tid = threadIdx.x;
    int pl = tid & 127, half = tid >> 7;
    int pix = p0 + pl;
    const float* tp = tmp + (size_t)bg*65536 + (size_t)half*32768 + pix;

    __shared__ float red[256], red2[256], mu_s[128], rs_s[128];

    float vals[32];
    float s1 = 0.f;
    #pragma unroll
    for (int i = 0; i < 32; i++) { vals[i] = tp[i*1024]; s1 += vals[i]; }
    red[tid] = s1;
    __syncthreads();
    if (half == 0) mu_s[pl] = (red[pl] + red[pl+128]) * (1.f/64.f);
    __syncthreads();
    float mu = mu_s[pl];
    float s2 = 0.f;
    #pragma unroll
    for (int i = 0; i < 32; i++) { float d = vals[i]-mu; s2 += d*d; }
    red[tid] = s2;
    __syncthreads();
    if (half == 0) rs_s[pl] = rsqrtf((red[pl]+red[pl+128])*(1.f/64.f) + 1e-5f);
    __syncthreads();
    float rs = rs_s[pl];
    float sy = 0.f, sx = 0.f;
    #pragma unroll
    for (int i = 0; i < 32; i++) {
        int cch = half*32 + i;
        float o = (vals[i]-mu)*rs*ln_g[cch] + ln_b[cch];
        o = 0.5f*o*(1.f + erff(o*0.70710678118654752f));
        sy += o * pw_w[cch];
        sx += o * pw_w[64+cch];
    }
    red[tid] = sy; red2[tid] = sx;
    __syncthreads();
    if (half == 0) {
        float oy = tanhf(red[pl]+red[pl+128]) * 0.0625f;
        float ox = tanhf(red2[pl]+red2[pl+128]) * 0.0625f;
        int py = pix >> 5, px = pix & 31;
        float refy = ((py + 0.5f)*(1.f/16.f)) - 1.f;
        float refx = ((px + 0.5f)*(1.f/16.f)) - 1.f;
        pos[bg*1024 + pix] = make_float2(ox + refx, oy + refy); // (x,y)
    }
}

// =======================================================================
// grid sample (round-2, channel-major in/out)
// =======================================================================
__global__ __launch_bounds__(256) void sample_kernel(
    const float* __restrict__ x, const float2* __restrict__ pos,
    float* __restrict__ xs)
{
    int idx = blockIdx.x * 256 + threadIdx.x;
    int s  = idx & 1023;
    int bg = idx >> 16;
    float2 p = pos[bg * 1024 + s];
    float gx = (p.x + 1.f) * 0.5f * 31.f;
    float gy = (p.y + 1.f) * 0.5f * 31.f;
    float x0f = floorf(gx), y0f = floorf(gy);
    float wx = gx - x0f, wy = gy - y0f;
    int x0 = (int)x0f, y0 = (int)y0f;
    const float* xp = x + (size_t)(idx >> 10) * 1024;
    float r = 0.f;
    bool vx0 = (x0 >= 0) & (x0 <= 31), vx1 = (x0 >= -1) & (x0 <= 30);
    bool vy0 = (y0 >= 0) & (y0 <= 31), vy1 = (y0 >= -1) & (y0 <= 30);
    if (vx0 && vy0) r += (1.f - wx) * (1.f - wy) * xp[y0 * 32 + x0];
    if (vx1 && vy0) r += wx * (1.f - wy) * xp[y0 * 32 + x0 + 1];
    if (vx0 && vy1) r += (1.f - wx) * wy * xp[(y0 + 1) * 32 + x0];
    if (vx1 && vy1) r += wx * wy * xp[(y0 + 1) * 32 + x0 + 1];
    xs[idx] = r;
}

// =======================================================================
// fused attention (round-2, channel-major, M=16 rows per block)
// smem floats: p[1024*20] | v[128*36] | q[512] | redw[128] | fin[32]
// =======================================================================
#define P_STRIDE 20
#define V_STRIDE 36
__global__ __launch_bounds__(256, 2) void attn_kernel(
    const float* __restrict__ qg, const float* __restrict__ kg,
    const float* __restrict__ vg, const float2* __restrict__ pos,
    const float* __restrict__ rpe, float* __restrict__ out)
{
    extern __shared__ float sm[];
    float* p_s  = sm;                       // 20480
    float* v_s  = sm + 20480;               // 4608
    float* q_s  = sm + 20480 + 4608;        // 512  [c*16 + r]
    float* redw = q_s + 512;                // 128  [r*8 + warp]
    float* fin  = redw + 128;               // 32

    int bh = blockIdx.y;
    int m0 = blockIdx.x * 16;
    int head = bh % 12;
    int bg = (bh / 12) * 6 + (head >> 1);
    int tid = threadIdx.x;
    int lane = tid & 31, warp = tid >> 5;

    #pragma unroll
    for (int i = tid; i < 512; i += 256) {
        int c = i >> 4, r = i & 15;
        q_s[i] = qg[(size_t)(bh*32 + c)*1024 + m0 + r] * SCALE;
    }
    __syncthreads();

    float acc[16][4] = {};
    const float* kb = kg + (size_t)bh * 32768;
    #pragma unroll 4
    for (int c = 0; c < 32; c++) {
        float k0 = kb[c*1024 + tid];
        float k1 = kb[c*1024 + tid + 256];
        float k2 = kb[c*1024 + tid + 512];
        float k3 = kb[c*1024 + tid + 768];
        #pragma unroll
        for (int r = 0; r < 16; r++) {
            float qv = q_s[c*16 + r];
            acc[r][0] = fmaf(qv, k0, acc[r][0]);
            acc[r][1] = fmaf(qv, k1, acc[r][1]);
            acc[r][2] = fmaf(qv, k2, acc[r][2]);
            acc[r][3] = fmaf(qv, k3, acc[r][3]);
        }
    }

    { // RPE bilinear bias (y constant over the 16 rows of this block)
        const float* T = rpe + head * 3969;
        int yq = m0 >> 5, xb = m0 & 31;
        float qy  = (yq + 0.5f) * (1.f/16.f) - 1.f;
        float qx0 = (xb + 0.5f) * (1.f/16.f) - 1.f;
        #pragma unroll
        for (int j = 0; j < 4; j++) {
            float2 p = pos[bg*1024 + tid + 256*j];
            float gy = fmaf(qy - p.y, 15.5f, 31.f);
            float y0f = floorf(gy);
            float wy = gy - y0f;
            int y0 = (int)y0f;
            float vy0 = (y0 >= 0 && y0 <= 62) ? 1.f : 0.f;
            float vy1 = (y0 >= -1 && y0 <= 61) ? 1.f : 0.f;
            int yc0 = min(max(y0, 0), 62);
            int yc1 = min(max(y0 + 1, 0), 62);
            const float* T0 = T + yc0*63;
            const float* T1 = T + yc1*63;
            float w0y = (1.f - wy) * vy0;
            float w1y = wy * vy1;
            float Cx = fmaf(qx0 - p.x, 15.5f, 31.f);
            #pragma unroll
            for (int r = 0; r < 16; r++) {
                float gx = fmaf((float)r, 0.96875f, Cx);
                float x0f = floorf(gx);
                float wx = gx - x0f;
                int x0 = (int)x0f;
                float vx0 = (x0 >= 0 && x0 <= 62) ? 1.f : 0.f;
                float vx1 = (x0 >= -1 && x0 <= 61) ? 1.f : 0.f;
                int xc0 = min(max(x0, 0), 62);
                int xc1 = min(max(x0 + 1, 0), 62);
                float t00 = T0[xc0], t01 = T0[xc1];
                float t10 = T1[xc0], t11 = T1[xc1];
                float wx0 = (1.f - wx) * vx0, wx1 = wx * vx1;
                acc[r][j] += w0y * (wx0*t00 + wx1*t01) + w1y * (wx0*t10 + wx1*t11);
            }
        }
    }

    // softmax
    float rv[16];
    #pragma unroll
    for (int r = 0; r < 16; r++)
        rv[r] = fmaxf(fmaxf(acc[r][0], acc[r][1]), fmaxf(acc[r][2], acc[r][3]));
    #pragma unroll
    for (int off = 16; off >= 1; off >>= 1)
        #pragma unroll
        for (int r = 0; r < 16; r++)
            rv[r] = fmaxf(rv[r], __shfl_xor_sync(0xffffffffu, rv[r], off));
    if (lane == 0)
        #pragma unroll
        for (int r = 0; r < 16; r++) redw[r*8 + warp] = rv[r];
    __syncthreads();
    if (tid < 16) {
        float m = redw[tid*8];
        #pragma unroll
        for (int w = 1; w < 8; w++) m = fmaxf(m, redw[tid*8 + w]);
        fin[tid] = m;
    }
    __syncthreads();
    #pragma unroll
    for (int r = 0; r < 16; r++) {
        float m = fin[r];
        float s = 0.f;
        #pragma unroll
        for (int j = 0; j < 4; j++) { acc[r][j] = __expf(acc[r][j] - m); s += acc[r][j]; }
        rv[r] = s;
    }
    #pragma unroll
    for (int off = 16; off >= 1; off >>= 1)
        #pragma unroll
        for (int r = 0; r < 16; r++)
            rv[r] += __shfl_xor_sync(0xffffffffu, rv[r], off);
    if (lane == 0)
        #pragma unroll
        for (int r = 0; r < 16; r++) redw[r*8 + warp] = rv[r];
    __syncthreads();
    if (tid < 16) {
        float s = 0.f;
        #pragma unroll
        for (int w = 0; w < 8; w++) s += redw[tid*8 + w];
        fin[16 + tid] = 1.f / s;
    }

    // store exp'd p transposed: p_s[n][r], stride 20
    #pragma unroll
    for (int j = 0; j < 4; j++) {
        int n = tid + 256*j;
        #pragma unroll
        for (int rq = 0; rq < 4; rq++)
            *(float4*)&p_s[n*P_STRIDE + rq*4] =
                make_float4(acc[rq*4+0][j], acc[rq*4+1][j], acc[rq*4+2][j], acc[rq*4+3][j]);
    }
    __syncthreads();

    // PV
    int combo = tid >> 3;
    int split = tid & 7;
    int cq = (combo & 7) * 4;
    int rq = (combo >> 3) * 4;
    float o4[4][4] = {};
    const float* vb = vg + (size_t)bh * 32768;

    int lc = tid & 31;
    int nb = (tid >> 5) * 16;
    #pragma unroll 1
    for (int chk = 0; chk < 8; chk++) {
        #pragma unroll
        for (int ii = 0; ii < 16; ii += 4) {
            float4 t = *(const float4*)(vb + lc*1024 + chk*128 + nb + ii);
            v_s[(nb+ii+0)*V_STRIDE + lc] = t.x;
            v_s[(nb+ii+1)*V_STRIDE + lc] = t.y;
            v_s[(nb+ii+2)*V_STRIDE + lc] = t.z;
            v_s[(nb+ii+3)*V_STRIDE + lc] = t.w;
        }
        __syncthreads();
        #pragma unroll
        for (int i = 0; i < 16; i++) {
            int nl = i*8 + split;
            float4 p4 = *(const float4*)&p_s[(chk*128 + nl)*P_STRIDE + rq];
            float4 v4 = *(const float4*)&v_s[nl*V_STRIDE + cq];
            o4[0][0] = fmaf(p4.x, v4.x, o4[0][0]); o4[0][1] = fmaf(p4.x, v4.y, o4[0][1]);
            o4[0][2] = fmaf(p4.x, v4.z, o4[0][2]); o4[0][3] = fmaf(p4.x, v4.w, o4[0][3]);
            o4[1][0] = fmaf(p4.y, v4.x, o4[1][0]); o4[1][1] = fmaf(p4.y, v4.y, o4[1][1]);
            o4[1][2] = fmaf(p4.y, v4.z, o4[1][2]); o4[1][3] = fmaf(p4.y, v4.w, o4[1][3]);
            o4[2][0] = fmaf(p4.z, v4.x, o4[2][0]); o4[2][1] = fmaf(p4.z, v4.y, o4[2][1]);
            o4[2][2] = fmaf(p4.z, v4.z, o4[2][2]); o4[2][3] = fmaf(p4.z, v4.w, o4[2][3]);
            o4[3][0] = fmaf(p4.w, v4.x, o4[3][0]); o4[3][1] = fmaf(p4.w, v4.y, o4[3][1]);
            o4[3][2] = fmaf(p4.w, v4.z, o4[3][2]); o4[3][3] = fmaf(p4.w, v4.w, o4[3][3]);
        }
        __syncthreads();
    }
    #pragma unroll
    for (int off = 4; off >= 1; off >>= 1)
        #pragma unroll
        for (int ri = 0; ri < 4; ri++)
            #pragma unroll
            for (int ci = 0; ci < 4; ci++)
                o4[ri][ci] += __shfl_xor_sync(0xffffffffu, o4[ri][ci], off);
    if (split == 0) {
        #pragma unroll
        for (int ri = 0; ri < 4; ri++) {
            float inv = fin[16 + rq + ri];
            #pragma unroll
            for (int ci = 0; ci < 4; ci++)
                out[(size_t)(bh*32 + cq + ci)*1024 + m0 + rq + ri] = o4[ri][ci] * inv;
        }
    }
}

// ---------------- launch ----------------
extern "C" void kernel_launch(void* const* d_in, const int* in_sizes, int n_in,
                              void* d_out, int out_size)
{
    const float* x    = (const float*)d_in[0];
    const float* Wq   = (const float*)d_in[1];
    const float* bq   = (const float*)d_in[2];
    const float* Wk   = (const float*)d_in[3];
    const float* bk   = (const float*)d_in[4];
    const float* Wv   = (const float*)d_in[5];
    const float* bv   = (const float*)d_in[6];
    const float* Wo   = (const float*)d_in[7];
    const float* bo   = (const float*)d_in[8];
    const float* dw_w = (const float*)d_in[9];
    const float* dw_b = (const float*)d_in[10];
    const float* ln_g = (const float*)d_in[11];
    const float* ln_b = (const float*)d_in[12];
    const float* pw_w = (const float*)d_in[13];
    const float* rpe  = (const float*)d_in[14];

    float *q, *xs, *k, *v, *ob;
    float2* pos;
    cudaGetSymbolAddress((void**)&q,   g_q);
    cudaGetSymbolAddress((void**)&xs,  g_xs);
    cudaGetSymbolAddress((void**)&k,   g_k);
    cudaGetSymbolAddress((void**)&v,   g_v);
    cudaGetSymbolAddress((void**)&ob,  g_o);
    cudaGetSymbolAddress((void**)&pos, g_pos);

    const int GSM = (2*64*AS_STRIDE + 2*32*BS_STRIDE) * 4;   // 53248 B
    cudaFuncSetAttribute(gemm_mma, cudaFuncAttributeMaxDynamicSharedMemorySize, GSM);
    cudaFuncSetAttribute(gemm_mma_kv, cudaFuncAttributeMaxDynamicSharedMemorySize, GSM);
    const int ASM = (20480 + 4608 + 512 + 128 + 32) * 4;     // 103040 B
    cudaFuncSetAttribute(attn_kernel, cudaFuncAttributeMaxDynamicSharedMemorySize, ASM);

    // Q = Wq x  (channel-major everywhere)
    gemm_mma<<<dim3(8, 6, 2), 256, GSM>>>(Wq, bq, x, q);
    // offset branch (k buffer as tmp)
    dwconv_kernel<<<768, 256>>>(q, dw_w, dw_b, k);
    offs_kernel<<<96, 256>>>(k, ln_g, ln_b, pw_w, pos);
    // sample
    sample_kernel<<<3072, 256>>>(x, pos, xs);
    // K, V
    gemm_mma_kv<<<dim3(8, 12, 2), 256, GSM>>>(Wk, bk, Wv, bv, xs, k, v);
    // attention
    attn_kernel<<<dim3(64, 24), 256, ASM>>>(q, k, v, pos, rpe, ob);
    // output projection
    gemm_mma<<<dim3(8, 6, 2), 256, GSM>>>(Wo, bo, ob, (float*)d_out);
}